// round 15
// baseline (speedup 1.0000x reference)
#include <cuda_runtime.h>
#include <cuda_fp16.h>
#include <cstdint>

typedef unsigned int u32;
typedef unsigned long long u64;

#define C_IN   64
#define C_OUT  128
#define KK     27
#define KKP    28                  // padded (tap 27 = zeros)
#define NP     14                  // double-tap pairs
#define HH     100000
#define TILE_H 64
#define NBLK   ((HH + TILE_H - 1) / TILE_H)
#define NTHR   128                 // 4 warps: grid 2(h) x 2(o), warp tile 32x64

// smem: 128B rows + SW128 XOR swizzle
// pair stage (48KB): A0 +0 (8K), A1 +8K, B0 +16K (16K), B1 +32K
#define A_TILE 8192
#define B_TILE 16384
#define STAGE  49152
#define NSTAGE 2
#define TILES_OFF 7168             // sIdx = 64*28*4 = 7168 B
#define SMEM_BYTES (TILES_OFF + NSTAGE * STAGE)   // 105472 -> 2 CTAs/SM

#define SWZ(o) ((o) ^ (((o) >> 3) & 0x70))

// ---------------- device scratch ----------------
__device__ __half g_x[(size_t)HH * C_IN];      // [h][c] fp16
__device__ __half g_w[KKP * C_OUT * C_IN];     // [k][o][c] fp16, tap 27 zeroed
__device__ int g_is64;

// ---------------- helpers ----------------
__device__ __forceinline__ u32 smem_u32(const void* p) {
    u32 a;
    asm("{ .reg .u64 t; cvta.to.shared.u64 t, %1; cvt.u32.u64 %0, t; }" : "=r"(a) : "l"(p));
    return a;
}
__device__ __forceinline__ void ldsm4(u32* r, u32 addr) {
    asm volatile("ldmatrix.sync.aligned.m8n8.x4.shared.b16 {%0,%1,%2,%3}, [%4];"
                 : "=r"(r[0]), "=r"(r[1]), "=r"(r[2]), "=r"(r[3]) : "r"(addr));
}
__device__ __forceinline__ void mma_f32(float* d, const u32* a, const u32* b) {
    asm volatile("mma.sync.aligned.m16n8k16.row.col.f32.f16.f16.f32 "
                 "{%0,%1,%2,%3}, {%4,%5,%6,%7}, {%8,%9}, {%0,%1,%2,%3};"
                 : "+f"(d[0]), "+f"(d[1]), "+f"(d[2]), "+f"(d[3])
                 : "r"(a[0]), "r"(a[1]), "r"(a[2]), "r"(a[3]), "r"(b[0]), "r"(b[1]));
}
#define CP16(dst, src) \
    asm volatile("cp.async.cg.shared.global [%0], [%1], 16;" ::"r"(dst), "l"(src) : "memory")
#define CP16Z(dst, src, sz) \
    asm volatile("cp.async.cg.shared.global [%0], [%1], 16, %2;" ::"r"(dst), "l"(src), "r"(sz) : "memory")
#define CP_COMMIT()  asm volatile("cp.async.commit_group;" ::: "memory")
#define CP_WAITALL() asm volatile("cp.async.wait_group 0;" ::: "memory")

// ---------------- prep kernels ----------------
__global__ void detect_dtype(const long long* __restrict__ n64) {
    if (threadIdx.x == 0 && blockIdx.x == 0) {
        int ok = 1;
        for (int i = 0; i < 256; i++) {
            long long v = n64[i];
            if (v < -(long long)HH || v >= (long long)HH) { ok = 0; break; }
        }
        g_is64 = ok;
    }
}

// x[c*HH + h] -> g_x[h*64 + c]
__global__ void conv_x(const float* __restrict__ x) {
    __shared__ float tile[32][33];
    const int hb = blockIdx.x * 32, cb = blockIdx.y * 32;
    const int tx = threadIdx.x, ty = threadIdx.y;
#pragma unroll
    for (int i = 0; i < 32; i += 8) {
        int h = hb + tx;
        tile[ty + i][tx] = (h < HH) ? x[(size_t)(cb + ty + i) * HH + h] : 0.f;
    }
    __syncthreads();
#pragma unroll
    for (int i = 0; i < 32; i += 8) {
        int h = hb + ty + i, c = cb + tx;
        if (h < HH) g_x[(size_t)h * C_IN + c] = __float2half(tile[tx][ty + i]);
    }
}

// w[o*1728 + c*27 + k] -> g_w[k*8192 + o*64 + c]; tap 27 zeroed
__global__ void conv_w(const float* __restrict__ w) {
    int idx = blockIdx.x * blockDim.x + threadIdx.x;
    if (idx >= KKP * C_OUT * C_IN) return;
    int k = idx / (C_OUT * C_IN);
    int rem = idx % (C_OUT * C_IN);
    int o = rem / C_IN, c = rem % C_IN;
    g_w[idx] = (k < KK) ? __float2half(w[(size_t)o * (C_IN * KK) + c * KK + k])
                        : __float2half(0.f);
}

// ---------------- main kernel ----------------
__global__ __launch_bounds__(NTHR, 2)
void conv_mma(const void* __restrict__ neigh_raw, float* __restrict__ out) {
    extern __shared__ char smem[];
    const u32 sbase = smem_u32(smem);
    int* sIdx = (int*)smem;                       // [64][28]
    const u32 tiles = sbase + TILES_OFF;

    const int tid = threadIdx.x;
    const int lid = tid & 31, wid = tid >> 5;     // 4 warps
    const int wr = wid & 1, wc = wid >> 1;        // 2(h) x 2(o)
    const int hb = blockIdx.x * TILE_H;

    // ---- stage neighbor indices (padded tap 27 -> -1) ----
    {
        const int is64 = g_is64;
        const long long* n64 = (const long long*)neigh_raw;
        const int* n32 = (const int*)neigh_raw;
        for (int j = tid; j < TILE_H * KKP; j += NTHR) {
            int hl = j / KKP, kk = j % KKP;
            int n = -1;
            if (kk < KK && hb + hl < HH) {
                size_t gi = (size_t)(hb + hl) * KK + kk;
                long long v = is64 ? n64[gi] : (long long)n32[gi];
                if (v >= 0 && v < HH) n = (int)v;
            }
            sIdx[j] = n;
        }
    }
    __syncthreads();

    // ---- per-thread load roles: A = 2 threads per row, 4 x 16B each ----
    const int ar   = tid >> 1;                 // gather row 0..63
    const int jgrp = (tid & 1) * 4;            // chunk group

    // ---- ldmatrix address precompute ----
    const u32 a_ro = (u32)(lid & 15);
    const u32 a_co = (u32)(lid >> 4);
    const u32 b_ro = (u32)((lid & 7) + ((lid >> 4) << 3));
    const u32 b_co = (u32)((lid >> 3) & 1);
    const u32 a_row = (u32)(wr * 32) + a_ro;
    const u32 b_row = (u32)(wc * 64) + b_ro;
    const u32 axor = (a_row & 7) * 16;
    const u32 bxor = (b_row & 7) * 16;
    const u32 arow0 = a_row * 128, arow1 = (a_row + 16) * 128;
    u32 brow[4];
#pragma unroll
    for (int g = 0; g < 4; g++) brow[g] = (b_row + g * 16) * 128;
    u32 koffA[4], koffB[4];
#pragma unroll
    for (int ks = 0; ks < 4; ks++) {
        koffA[ks] = ((u32)(ks * 32) + a_co * 16) ^ axor;
        koffB[ks] = ((u32)(ks * 32) + b_co * 16) ^ bxor;
    }

    float acc[2][8][4];                        // 32h x 64o per warp
#pragma unroll
    for (int mf = 0; mf < 2; mf++)
#pragma unroll
        for (int nf = 0; nf < 8; nf++)
#pragma unroll
            for (int r = 0; r < 4; r++) acc[mf][nf][r] = 0.f;

    // ---- issue one PAIR of taps (2p, 2p+1) into stage s ----
    auto issue = [&](int p, int s) {
        const u32 st = tiles + s * STAGE;
        const int k0 = 2 * p;
        const u32 rowoff = (u32)ar * 128 + (u32)jgrp * 16;
        // A: 2 taps x 64 rows x 128B; this thread does 4 x 16B per tap
#pragma unroll
        for (int t = 0; t < 2; t++) {
            int n = sIdx[ar * KKP + k0 + t];
            const char* src = (const char*)(g_x + (n < 0 ? 0 : (size_t)n * C_IN)) + jgrp * 16;
            u32 sz = (n < 0) ? 0u : 16u;
            const u32 dst = st + t * A_TILE;
#pragma unroll
            for (int j = 0; j < 4; j++)
                CP16Z(dst + SWZ(rowoff + j * 16), src + j * 16, sz);
        }
        // B: 2 weight taps, 16KB each, 8 chunks per thread per tap
#pragma unroll
        for (int t = 0; t < 2; t++) {
            const char* bs = (const char*)(g_w + (size_t)(k0 + t) * (C_OUT * C_IN));
            const u32 dst = st + 2 * A_TILE + t * B_TILE;
#pragma unroll
            for (int i = 0; i < 8; i++) {
                int cc = tid + i * NTHR;
                CP16(dst + SWZ((u32)cc * 16), bs + cc * 16);
            }
        }
    };

    issue(0, 0); CP_COMMIT();

    for (int p = 0; p < NP; p++) {
        const int s = p & 1;
        CP_WAITALL();                           // pair p's data landed
        __syncthreads();                        // all warps done reading pair p-1

        if (p + 1 < NP) { issue(p + 1, s ^ 1); CP_COMMIT(); }

        const u32 st = tiles + s * STAGE;
#pragma unroll
        for (int t = 0; t < 2; t++) {
            const u32 stA = st + t * A_TILE;
            const u32 stB = st + 2 * A_TILE + t * B_TILE;
#pragma unroll
            for (int ks = 0; ks < 4; ks++) {
                u32 a[2][4], b[4][4];
                ldsm4(a[0], stA + arow0 + koffA[ks]);
                ldsm4(a[1], stA + arow1 + koffA[ks]);
#pragma unroll
                for (int g = 0; g < 4; g++)
                    ldsm4(b[g], stB + brow[g] + koffB[ks]);
#pragma unroll
                for (int mf = 0; mf < 2; mf++)
#pragma unroll
                    for (int g = 0; g < 4; g++) {
                        mma_f32(acc[mf][2 * g],     a[mf], &b[g][0]);
                        mma_f32(acc[mf][2 * g + 1], a[mf], &b[g][2]);
                    }
            }
        }
    }

    __syncthreads();   // all warps done; sC aliases tile smem
    // ---- epilogue: relu, stage via smem [o][h] pitch 68, coalesced stores ----
    float* sC = (float*)(smem + TILES_OFF);
#pragma unroll
    for (int mf = 0; mf < 2; mf++)
#pragma unroll
        for (int nf = 0; nf < 8; nf++)
#pragma unroll
            for (int r = 0; r < 4; r++) {
                int m = wr * 32 + mf * 16 + (lid >> 2) + ((r >> 1) << 3);
                int n = wc * 64 + nf * 8 + ((lid & 3) << 1) + (r & 1);
                sC[n * 68 + m] = fmaxf(acc[mf][nf][r], 0.f);
            }
    __syncthreads();
#pragma unroll
    for (int it = 0; it < 16; it++) {
        int idx = it * NTHR + tid;               // 2048 float4
        int o = idx >> 4, hq = idx & 15;
        int h = hb + hq * 4;
        if (h < HH) {
            float4 v = *(const float4*)(sC + o * 68 + hq * 4);
            *(float4*)(out + (size_t)o * HH + h) = v;
        }
    }
}

// ---------------- launch ----------------
extern "C" void kernel_launch(void* const* d_in, const int* in_sizes, int n_in,
                              void* d_out, int out_size) {
    const float* x = (const float*)d_in[0];
    const void* neigh = d_in[1];
    const float* w = (const float*)d_in[2];
    float* out = (float*)d_out;

    cudaFuncSetAttribute(conv_mma, cudaFuncAttributeMaxDynamicSharedMemorySize, SMEM_BYTES);

    detect_dtype<<<1, 32>>>((const long long*)neigh);
    conv_x<<<dim3((HH + 31) / 32, C_IN / 32), dim3(32, 8)>>>(x);
    conv_w<<<(KKP * C_OUT * C_IN + 255) / 256, 256>>>(w);
    conv_mma<<<NBLK, NTHR, SMEM_BYTES>>>(neigh, out);
}

// round 16
// speedup vs baseline: 1.1284x; 1.1284x over previous
#include <cuda_runtime.h>
#include <cuda_fp16.h>
#include <cstdint>

typedef unsigned int u32;
typedef unsigned long long u64;

#define C_IN   64
#define C_OUT  128
#define KK     27
#define HH     100000
#define TILE_H 64
#define NBLK   ((HH + TILE_H - 1) / TILE_H)
#define NTHR   128                 // 4 warps: 2(h) x 2(o), warp tile 32x64

// smem: 128B rows + SW128 XOR swizzle
// single-tap stage (24KB): A +0 (8K), B +8K (16K); double-buffered
#define A_TILE 8192
#define B_TILE 16384
#define STAGE  24576
#define NSTAGE 2
#define TILES_OFF 7168             // sIdx = 64*27*4 = 6912 B, padded
#define SMEM_BYTES (TILES_OFF + NSTAGE * STAGE)   // 56320 -> 3 CTAs/SM

#define SWZ(o) ((o) ^ (((o) >> 3) & 0x70))

// ---------------- device scratch ----------------
__device__ __half g_x[(size_t)HH * C_IN];      // [h][c] fp16
__device__ __half g_w[KK * C_OUT * C_IN];      // [k][o][c] fp16
__device__ int g_is64;

// ---------------- helpers ----------------
__device__ __forceinline__ u32 smem_u32(const void* p) {
    u32 a;
    asm("{ .reg .u64 t; cvta.to.shared.u64 t, %1; cvt.u32.u64 %0, t; }" : "=r"(a) : "l"(p));
    return a;
}
__device__ __forceinline__ void ldsm4(u32* r, u32 addr) {
    asm volatile("ldmatrix.sync.aligned.m8n8.x4.shared.b16 {%0,%1,%2,%3}, [%4];"
                 : "=r"(r[0]), "=r"(r[1]), "=r"(r[2]), "=r"(r[3]) : "r"(addr));
}
__device__ __forceinline__ void mma_f32(float* d, const u32* a, const u32* b) {
    asm volatile("mma.sync.aligned.m16n8k16.row.col.f32.f16.f16.f32 "
                 "{%0,%1,%2,%3}, {%4,%5,%6,%7}, {%8,%9}, {%0,%1,%2,%3};"
                 : "+f"(d[0]), "+f"(d[1]), "+f"(d[2]), "+f"(d[3])
                 : "r"(a[0]), "r"(a[1]), "r"(a[2]), "r"(a[3]), "r"(b[0]), "r"(b[1]));
}
#define CP16(dst, src) \
    asm volatile("cp.async.cg.shared.global [%0], [%1], 16;" ::"r"(dst), "l"(src) : "memory")
#define CP16Z(dst, src, sz) \
    asm volatile("cp.async.cg.shared.global [%0], [%1], 16, %2;" ::"r"(dst), "l"(src), "r"(sz) : "memory")
#define CP_COMMIT()  asm volatile("cp.async.commit_group;" ::: "memory")
#define CP_WAITALL() asm volatile("cp.async.wait_group 0;" ::: "memory")

// ---------------- prep kernels ----------------
__global__ void detect_dtype(const long long* __restrict__ n64) {
    if (threadIdx.x == 0 && blockIdx.x == 0) {
        int ok = 1;
        for (int i = 0; i < 256; i++) {
            long long v = n64[i];
            if (v < -(long long)HH || v >= (long long)HH) { ok = 0; break; }
        }
        g_is64 = ok;
    }
}

// x[c*HH + h] -> g_x[h*64 + c]
__global__ void conv_x(const float* __restrict__ x) {
    __shared__ float tile[32][33];
    const int hb = blockIdx.x * 32, cb = blockIdx.y * 32;
    const int tx = threadIdx.x, ty = threadIdx.y;
#pragma unroll
    for (int i = 0; i < 32; i += 8) {
        int h = hb + tx;
        tile[ty + i][tx] = (h < HH) ? x[(size_t)(cb + ty + i) * HH + h] : 0.f;
    }
    __syncthreads();
#pragma unroll
    for (int i = 0; i < 32; i += 8) {
        int h = hb + ty + i, c = cb + tx;
        if (h < HH) g_x[(size_t)h * C_IN + c] = __float2half(tile[tx][ty + i]);
    }
}

// w[o*1728 + c*27 + k] -> g_w[k*8192 + o*64 + c]
__global__ void conv_w(const float* __restrict__ w) {
    int idx = blockIdx.x * blockDim.x + threadIdx.x;
    if (idx >= KK * C_OUT * C_IN) return;
    int k = idx / (C_OUT * C_IN);
    int rem = idx % (C_OUT * C_IN);
    int o = rem / C_IN, c = rem % C_IN;
    g_w[idx] = __float2half(w[(size_t)o * (C_IN * KK) + c * KK + k]);
}

// ---------------- main kernel ----------------
__global__ __launch_bounds__(NTHR, 3)
void conv_mma(const void* __restrict__ neigh_raw, float* __restrict__ out) {
    extern __shared__ char smem[];
    const u32 sbase = smem_u32(smem);
    int* sIdx = (int*)smem;                       // [64][27]
    const u32 tiles = sbase + TILES_OFF;

    const int tid = threadIdx.x;
    const int lid = tid & 31, wid = tid >> 5;     // 4 warps
    const int wr = wid & 1, wc = wid >> 1;        // 2(h) x 2(o)
    const int hb = blockIdx.x * TILE_H;

    // ---- stage neighbor indices ----
    {
        const int is64 = g_is64;
        const long long* n64 = (const long long*)neigh_raw;
        const int* n32 = (const int*)neigh_raw;
        for (int j = tid; j < TILE_H * KK; j += NTHR) {
            int hl = j / KK;
            int n = -1;
            if (hb + hl < HH) {
                size_t gi = (size_t)(hb + hl) * KK + (j % KK);
                long long v = is64 ? n64[gi] : (long long)n32[gi];
                if (v >= 0 && v < HH) n = (int)v;
            }
            sIdx[j] = n;
        }
    }
    __syncthreads();

    // ---- per-thread load roles: A = 2 threads per row, 4 x 16B each ----
    const int ar   = tid >> 1;                 // gather row 0..63
    const int jgrp = (tid & 1) * 4;            // chunk group

    // ---- ldmatrix address precompute ----
    const u32 a_ro = (u32)(lid & 15);
    const u32 a_co = (u32)(lid >> 4);
    const u32 b_ro = (u32)((lid & 7) + ((lid >> 4) << 3));
    const u32 b_co = (u32)((lid >> 3) & 1);
    const u32 a_row = (u32)(wr * 32) + a_ro;
    const u32 b_row = (u32)(wc * 64) + b_ro;
    const u32 axor = (a_row & 7) * 16;
    const u32 bxor = (b_row & 7) * 16;
    const u32 arow0 = a_row * 128, arow1 = (a_row + 16) * 128;
    u32 brow[4];
#pragma unroll
    for (int g = 0; g < 4; g++) brow[g] = (b_row + g * 16) * 128;
    u32 koffA[4], koffB[4];
#pragma unroll
    for (int ks = 0; ks < 4; ks++) {
        koffA[ks] = ((u32)(ks * 32) + a_co * 16) ^ axor;
        koffB[ks] = ((u32)(ks * 32) + b_co * 16) ^ bxor;
    }

    float acc[2][8][4];                        // 32h x 64o per warp
#pragma unroll
    for (int mf = 0; mf < 2; mf++)
#pragma unroll
        for (int nf = 0; nf < 8; nf++)
#pragma unroll
            for (int r = 0; r < 4; r++) acc[mf][nf][r] = 0.f;

    // ---- issue one tap k into stage s ----
    auto issue = [&](int k, int s) {
        const u32 st = tiles + s * STAGE;
        // A: this thread does 4 x 16B of its gather row
        int n = sIdx[ar * KK + k];
        const char* src = (const char*)(g_x + (n < 0 ? 0 : (size_t)n * C_IN)) + jgrp * 16;
        u32 sz = (n < 0) ? 0u : 16u;
        const u32 rowoff = (u32)ar * 128 + (u32)jgrp * 16;
#pragma unroll
        for (int j = 0; j < 4; j++)
            CP16Z(st + SWZ(rowoff + j * 16), src + j * 16, sz);
        // B: 1024 x 16B chunks, 8 per thread
        const char* bs = (const char*)(g_w + (size_t)k * (C_OUT * C_IN));
#pragma unroll
        for (int i = 0; i < 8; i++) {
            int cc = tid + i * NTHR;
            CP16(st + A_TILE + SWZ((u32)cc * 16), bs + cc * 16);
        }
    };

    issue(0, 0); CP_COMMIT();

    for (int k = 0; k < KK; k++) {
        const int s = k & 1;
        CP_WAITALL();                           // tap k's data landed
        __syncthreads();                        // all warps done reading tap k-1 -> stage s^1 free

        if (k + 1 < KK) { issue(k + 1, s ^ 1); CP_COMMIT(); }

        const u32 stA = tiles + s * STAGE;
        const u32 stB = stA + A_TILE;
#pragma unroll
        for (int ks = 0; ks < 4; ks++) {
            u32 a[2][4], b[4][4];
            ldsm4(a[0], stA + arow0 + koffA[ks]);
            ldsm4(a[1], stA + arow1 + koffA[ks]);
#pragma unroll
            for (int g = 0; g < 4; g++)
                ldsm4(b[g], stB + brow[g] + koffB[ks]);
#pragma unroll
            for (int mf = 0; mf < 2; mf++)
#pragma unroll
                for (int g = 0; g < 4; g++) {
                    mma_f32(acc[mf][2 * g],     a[mf], &b[g][0]);
                    mma_f32(acc[mf][2 * g + 1], a[mf], &b[g][2]);
                }
        }
    }

    __syncthreads();   // all warps done; sC aliases tile smem (34.8KB <= 48KB)
    // ---- epilogue: relu, stage via smem [o][h] pitch 68, coalesced stores ----
    float* sC = (float*)(smem + TILES_OFF);
#pragma unroll
    for (int mf = 0; mf < 2; mf++)
#pragma unroll
        for (int nf = 0; nf < 8; nf++)
#pragma unroll
            for (int r = 0; r < 4; r++) {
                int m = wr * 32 + mf * 16 + (lid >> 2) + ((r >> 1) << 3);
                int n = wc * 64 + nf * 8 + ((lid & 3) << 1) + (r & 1);
                sC[n * 68 + m] = fmaxf(acc[mf][nf][r], 0.f);
            }
    __syncthreads();
#pragma unroll
    for (int it = 0; it < 16; it++) {
        int idx = it * NTHR + tid;               // 2048 float4
        int o = idx >> 4, hq = idx & 15;
        int h = hb + hq * 4;
        if (h < HH) {
            float4 v = *(const float4*)(sC + o * 68 + hq * 4);
            *(float4*)(out + (size_t)o * HH + h) = v;
        }
    }
}

// ---------------- launch ----------------
extern "C" void kernel_launch(void* const* d_in, const int* in_sizes, int n_in,
                              void* d_out, int out_size) {
    const float* x = (const float*)d_in[0];
    const void* neigh = d_in[1];
    const float* w = (const float*)d_in[2];
    float* out = (float*)d_out;

    cudaFuncSetAttribute(conv_mma, cudaFuncAttributeMaxDynamicSharedMemorySize, SMEM_BYTES);

    detect_dtype<<<1, 32>>>((const long long*)neigh);
    conv_x<<<dim3((HH + 31) / 32, C_IN / 32), dim3(32, 8)>>>(x);
    conv_w<<<(KK * C_OUT * C_IN + 255) / 256, 256>>>(w);
    conv_mma<<<NBLK, NTHR, SMEM_BYTES>>>(neigh, out);
}

// round 17
// speedup vs baseline: 1.1396x; 1.0099x over previous
#include <cuda_runtime.h>
#include <cuda_fp16.h>
#include <cstdint>

typedef unsigned int u32;
typedef unsigned long long u64;

#define C_IN   64
#define C_OUT  128
#define KK     27
#define HH     100000
#define TILE_H 64
#define NBLK   ((HH + TILE_H - 1) / TILE_H)
#define NTHR   128                 // 4 warps: 2(h) x 2(o), warp tile 32x64

// smem: 128B rows + SW128 XOR swizzle
// single-tap stage (24KB): A +0 (8K), B +8K (16K); double-buffered
#define A_TILE 8192
#define B_TILE 16384
#define STAGE  24576
#define NSTAGE 2
#define FLAG_OFF  6912             // after sIdx (64*27*4)
#define TILES_OFF 7168
#define SMEM_BYTES (TILES_OFF + NSTAGE * STAGE)   // 56320 -> 3 CTAs/SM

#define SWZ(o) ((o) ^ (((o) >> 3) & 0x70))

// ---------------- device scratch ----------------
__device__ __half g_x[(size_t)HH * C_IN];      // [h][c] fp16
__device__ __half g_w[KK * C_OUT * C_IN];      // [k][o][c] fp16

// ---------------- helpers ----------------
__device__ __forceinline__ u32 smem_u32(const void* p) {
    u32 a;
    asm("{ .reg .u64 t; cvta.to.shared.u64 t, %1; cvt.u32.u64 %0, t; }" : "=r"(a) : "l"(p));
    return a;
}
__device__ __forceinline__ void ldsm4(u32* r, u32 addr) {
    asm volatile("ldmatrix.sync.aligned.m8n8.x4.shared.b16 {%0,%1,%2,%3}, [%4];"
                 : "=r"(r[0]), "=r"(r[1]), "=r"(r[2]), "=r"(r[3]) : "r"(addr));
}
__device__ __forceinline__ void mma_f32(float* d, const u32* a, const u32* b) {
    asm volatile("mma.sync.aligned.m16n8k16.row.col.f32.f16.f16.f32 "
                 "{%0,%1,%2,%3}, {%4,%5,%6,%7}, {%8,%9}, {%0,%1,%2,%3};"
                 : "+f"(d[0]), "+f"(d[1]), "+f"(d[2]), "+f"(d[3])
                 : "r"(a[0]), "r"(a[1]), "r"(a[2]), "r"(a[3]), "r"(b[0]), "r"(b[1]));
}
#define CP16(dst, src) \
    asm volatile("cp.async.cg.shared.global [%0], [%1], 16;" ::"r"(dst), "l"(src) : "memory")
#define CP16Z(dst, src, sz) \
    asm volatile("cp.async.cg.shared.global [%0], [%1], 16, %2;" ::"r"(dst), "l"(src), "r"(sz) : "memory")
#define CP_COMMIT()  asm volatile("cp.async.commit_group;" ::: "memory")
#define CP_WAITALL() asm volatile("cp.async.wait_group 0;" ::: "memory")

// ---------------- merged prep: x transpose+fp16, w reorder+fp16 ----------------
// grid (3125, 3), 256 thr. y=0,1: x transpose (cb = y*32). y=2: w reorder.
__global__ void conv_prep(const float* __restrict__ x, const float* __restrict__ w) {
    const int tid = threadIdx.x;
    if (blockIdx.y < 2) {
        __shared__ float tile[32][33];
        const int tx = tid & 31, ty = tid >> 5;          // 32 x 8
        const int hb = blockIdx.x * 32, cb = blockIdx.y * 32;
#pragma unroll
        for (int i = 0; i < 32; i += 8) {
            int h = hb + tx;
            tile[ty + i][tx] = (h < HH) ? x[(size_t)(cb + ty + i) * HH + h] : 0.f;
        }
        __syncthreads();
#pragma unroll
        for (int i = 0; i < 32; i += 8) {
            int h = hb + ty + i, c = cb + tx;
            if (h < HH) g_x[(size_t)h * C_IN + c] = __float2half(tile[tx][ty + i]);
        }
    } else {
        int idx = blockIdx.x * 256 + tid;
        if (idx < KK * C_OUT * C_IN) {
            int k = idx / (C_OUT * C_IN);
            int rem = idx % (C_OUT * C_IN);
            int o = rem / C_IN, c = rem % C_IN;
            g_w[idx] = __float2half(w[(size_t)o * (C_IN * KK) + c * KK + k]);
        }
    }
}

// ---------------- main kernel ----------------
__global__ __launch_bounds__(NTHR, 3)
void conv_mma(const void* __restrict__ neigh_raw, float* __restrict__ out) {
    extern __shared__ char smem[];
    const u32 sbase = smem_u32(smem);
    int* sIdx = (int*)smem;                       // [64][27]
    int* sFlag = (int*)(smem + FLAG_OFF);
    const u32 tiles = sbase + TILES_OFF;

    const int tid = threadIdx.x;
    const int lid = tid & 31, wid = tid >> 5;     // 4 warps
    const int wr = wid & 1, wc = wid >> 1;        // 2(h) x 2(o)
    const int hb = blockIdx.x * TILE_H;

    // ---- inline dtype detection (parallel vote over first 256 i64 words) ----
    if (tid == 0) *sFlag = 1;
    __syncthreads();
    {
        const long long* n64 = (const long long*)neigh_raw;
        long long v0 = n64[tid], v1 = n64[tid + NTHR];
        bool bad = (v0 < -(long long)HH || v0 >= (long long)HH ||
                    v1 < -(long long)HH || v1 >= (long long)HH);
        if (bad) atomicAnd(sFlag, 0);
    }
    __syncthreads();
    const int is64 = *sFlag;

    // ---- stage neighbor indices ----
    {
        const long long* n64 = (const long long*)neigh_raw;
        const int* n32 = (const int*)neigh_raw;
        for (int j = tid; j < TILE_H * KK; j += NTHR) {
            int hl = j / KK;
            int n = -1;
            if (hb + hl < HH) {
                size_t gi = (size_t)(hb + hl) * KK + (j % KK);
                long long v = is64 ? n64[gi] : (long long)n32[gi];
                if (v >= 0 && v < HH) n = (int)v;
            }
            sIdx[j] = n;
        }
    }
    __syncthreads();

    // ---- per-thread load roles: A = 2 threads per row, 4 x 16B each ----
    const int ar   = tid >> 1;                 // gather row 0..63
    const int jgrp = (tid & 1) * 4;            // chunk group

    // ---- ldmatrix address precompute ----
    const u32 a_ro = (u32)(lid & 15);
    const u32 a_co = (u32)(lid >> 4);
    const u32 b_ro = (u32)((lid & 7) + ((lid >> 4) << 3));
    const u32 b_co = (u32)((lid >> 3) & 1);
    const u32 a_row = (u32)(wr * 32) + a_ro;
    const u32 b_row = (u32)(wc * 64) + b_ro;
    const u32 axor = (a_row & 7) * 16;
    const u32 bxor = (b_row & 7) * 16;
    const u32 arow0 = a_row * 128, arow1 = (a_row + 16) * 128;
    u32 brow[4];
#pragma unroll
    for (int g = 0; g < 4; g++) brow[g] = (b_row + g * 16) * 128;
    u32 koffA[4], koffB[4];
#pragma unroll
    for (int ks = 0; ks < 4; ks++) {
        koffA[ks] = ((u32)(ks * 32) + a_co * 16) ^ axor;
        koffB[ks] = ((u32)(ks * 32) + b_co * 16) ^ bxor;
    }

    float acc[2][8][4];                        // 32h x 64o per warp
#pragma unroll
    for (int mf = 0; mf < 2; mf++)
#pragma unroll
        for (int nf = 0; nf < 8; nf++)
#pragma unroll
            for (int r = 0; r < 4; r++) acc[mf][nf][r] = 0.f;

    // ---- issue one tap k into stage s ----
    auto issue = [&](int k, int s) {
        const u32 st = tiles + s * STAGE;
        int n = sIdx[ar * KK + k];
        const char* src = (const char*)(g_x + (n < 0 ? 0 : (size_t)n * C_IN)) + jgrp * 16;
        u32 sz = (n < 0) ? 0u : 16u;
        const u32 rowoff = (u32)ar * 128 + (u32)jgrp * 16;
#pragma unroll
        for (int j = 0; j < 4; j++)
            CP16Z(st + SWZ(rowoff + j * 16), src + j * 16, sz);
        const char* bs = (const char*)(g_w + (size_t)k * (C_OUT * C_IN));
#pragma unroll
        for (int i = 0; i < 8; i++) {
            int cc = tid + i * NTHR;
            CP16(st + A_TILE + SWZ((u32)cc * 16), bs + cc * 16);
        }
    };

    issue(0, 0); CP_COMMIT();

    for (int k = 0; k < KK; k++) {
        const int s = k & 1;
        CP_WAITALL();                           // tap k's data landed
        __syncthreads();                        // all warps done reading tap k-1

        if (k + 1 < KK) { issue(k + 1, s ^ 1); CP_COMMIT(); }

        const u32 stA = tiles + s * STAGE;
        const u32 stB = stA + A_TILE;
#pragma unroll
        for (int ks = 0; ks < 4; ks++) {
            u32 a[2][4], b[4][4];
            ldsm4(a[0], stA + arow0 + koffA[ks]);
            ldsm4(a[1], stA + arow1 + koffA[ks]);
#pragma unroll
            for (int g = 0; g < 4; g++)
                ldsm4(b[g], stB + brow[g] + koffB[ks]);
#pragma unroll
            for (int mf = 0; mf < 2; mf++)
#pragma unroll
                for (int g = 0; g < 4; g++) {
                    mma_f32(acc[mf][2 * g],     a[mf], &b[g][0]);
                    mma_f32(acc[mf][2 * g + 1], a[mf], &b[g][2]);
                }
        }
    }

    __syncthreads();   // all warps done; sC aliases tile smem
    // ---- epilogue: relu, stage via smem [o][h] pitch 68, coalesced stores ----
    float* sC = (float*)(smem + TILES_OFF);
#pragma unroll
    for (int mf = 0; mf < 2; mf++)
#pragma unroll
        for (int nf = 0; nf < 8; nf++)
#pragma unroll
            for (int r = 0; r < 4; r++) {
                int m = wr * 32 + mf * 16 + (lid >> 2) + ((r >> 1) << 3);
                int n = wc * 64 + nf * 8 + ((lid & 3) << 1) + (r & 1);
                sC[n * 68 + m] = fmaxf(acc[mf][nf][r], 0.f);
            }
    __syncthreads();
#pragma unroll
    for (int it = 0; it < 16; it++) {
        int idx = it * NTHR + tid;               // 2048 float4
        int o = idx >> 4, hq = idx & 15;
        int h = hb + hq * 4;
        if (h < HH) {
            float4 v = *(const float4*)(sC + o * 68 + hq * 4);
            *(float4*)(out + (size_t)o * HH + h) = v;
        }
    }
}

// ---------------- launch ----------------
extern "C" void kernel_launch(void* const* d_in, const int* in_sizes, int n_in,
                              void* d_out, int out_size) {
    const float* x = (const float*)d_in[0];
    const void* neigh = d_in[1];
    const float* w = (const float*)d_in[2];
    float* out = (float*)d_out;

    cudaFuncSetAttribute(conv_mma, cudaFuncAttributeMaxDynamicSharedMemorySize, SMEM_BYTES);

    conv_prep<<<dim3((HH + 31) / 32, 3), 256>>>(x, w);
    conv_mma<<<NBLK, NTHR, SMEM_BYTES>>>(neigh, out);
}